// round 8
// baseline (speedup 1.0000x reference)
#include <cuda_runtime.h>
#include <cuda_bf16.h>

#define Hdim 512
#define Wdim 512
#define Qn 3
#define Pn 1024
#define Bn 64
#define JITTER 1e-6f

#define TS 18      // strip/row stride in float2 (16B-aligned strip bases)
#define REG 296    // float2 per group region (16*18=288 used, +8 pad)

// Precomputed symmetrized spectrum: S_sym[p][ky*16+kx] / 256
__device__ float g_S[Pn * 256];

// ---------------------------------------------------------------------------
// Kernel A: build S per patch (separable Gaussians), then index-symmetrize:
//   S_sym[k] = (S[k] + S[(-k) mod 16]) / 2    (makes Xf*S exactly Hermitian)
// ---------------------------------------------------------------------------
__global__ __launch_bounds__(256) void make_S_kernel(
    const float* __restrict__ logits,
    const float* __restrict__ mu,
    const float* __restrict__ sigma)
{
    __shared__ float w[4];
    __shared__ float gy[6][16];
    __shared__ float gx[6][16];
    __shared__ float sAcc[256];

    const int p = blockIdx.x;
    const int t = threadIdx.x;

    if (t == 0) {
        const float l0 = logits[p * Qn + 0];
        const float l1 = logits[p * Qn + 1];
        const float l2 = logits[p * Qn + 2];
        const float mx = fmaxf(l0, fmaxf(l1, l2));
        const float e0 = expf(l0 - mx);
        const float e1 = expf(l1 - mx);
        const float e2 = expf(l2 - mx);
        const float inv = 1.0f / (e0 + e1 + e2);
        w[0] = e0 * inv; w[1] = e1 * inv; w[2] = e2 * inv;
    }
    if (t < 192) {
        const int axis = t / 96;
        const int rem  = t % 96;
        const int qs   = rem >> 4;
        const int k    = rem & 15;
        const int q    = qs >> 1;
        const int sgn  = qs & 1;
        const float f  = (float)(k < 8 ? k : k - 16) * (1.0f / 16.0f);
        const int base = (p * Qn + q) * 2;
        const float m  = mu[base + axis];
        const float s  = sigma[base + axis];
        const float d  = (sgn ? (f + m) : (f - m)) / s;
        const float v  = expf(-0.5f * d * d);
        if (axis == 0) gy[qs][k] = v; else gx[qs][k] = v;
    }
    __syncthreads();

    const int ky = t >> 4;
    const int kx = t & 15;
    float acc = 0.0f;
#pragma unroll
    for (int q = 0; q < Qn; ++q) {
        acc += w[q] * (gy[2 * q][ky] * gx[2 * q][kx] +
                       gy[2 * q + 1][ky] * gx[2 * q + 1][kx]);
    }
    sAcc[t] = acc;
    __syncthreads();

    const int tm = (((16 - ky) & 15) << 4) | ((16 - kx) & 15);
    const float ssym = 0.5f * (sAcc[t] + sAcc[tm]) + JITTER;
    g_S[p * 256 + t] = ssym * (1.0f / 256.0f);
}

// ---------------------------------------------------------------------------
// Fully unrolled 16-point complex FFT. DIR=-1 fwd, DIR=+1 inv (unnormalized).
// ---------------------------------------------------------------------------
template<int DIR>
__device__ __forceinline__ void fft16(float re[16], float im[16]) {
#define SWAPF(a,b) { float _t=re[a]; re[a]=re[b]; re[b]=_t; _t=im[a]; im[a]=im[b]; im[b]=_t; }
    SWAPF(1, 8) SWAPF(2, 4) SWAPF(3, 12) SWAPF(5, 10) SWAPF(7, 14) SWAPF(11, 13)
#undef SWAPF
    const float CT[8] = { 1.0f,  0.9238795325112867f,  0.7071067811865476f,  0.3826834323650898f,
                          0.0f, -0.3826834323650898f, -0.7071067811865476f, -0.9238795325112867f };
    const float ST[8] = { 0.0f,  0.3826834323650898f,  0.7071067811865476f,  0.9238795325112867f,
                          1.0f,  0.9238795325112867f,  0.7071067811865476f,  0.3826834323650898f };
#pragma unroll
    for (int s = 1; s <= 4; ++s) {
        const int len   = 1 << s;
        const int half  = len >> 1;
        const int tstep = 16 >> s;
#pragma unroll
        for (int i = 0; i < 16; i += len) {
#pragma unroll
            for (int j = 0; j < half; ++j) {
                const float c  = CT[j * tstep];
                const float sn = (float)DIR * ST[j * tstep];
                const int a = i + j;
                const int b = a + half;
                float br = re[b], bi = im[b];
                float tr = c * br - sn * bi;
                float ti = c * bi + sn * br;
                re[b] = re[a] - tr;
                im[b] = im[a] - ti;
                re[a] += tr;
                im[a] += ti;
            }
        }
    }
}

// ---------------------------------------------------------------------------
// Kernel B: block = one adjacent patch pair (A,B) x 16 batches.
// Round 8: strips use stride-18 float2 so phase-2 and phase-3 read with
// LDS.128 (strip-major write, row-major write-back between them).
// ---------------------------------------------------------------------------
__global__ __launch_bounds__(256, 4) void patch_spectral_kernel(
    const float* __restrict__ x,
    const float* __restrict__ bias,
    float* __restrict__ y)
{
    __shared__ float2 colbuf[16][REG];   // per group: stage (576 f) / strips (288 f2)
    __shared__ float  sSt[2][336];       // transposed S: sSt[h][kx*20+ky]

    const int pp = blockIdx.x & 511;     // patch-pair index
    const int bg = blockIdx.x >> 9;      // batch group (16 batches)
    const int t  = threadIdx.x;
    const int p0 = pp * 2;

    const int wrp = t >> 5;       // warp 0..7
    const int l   = t & 31;       // lane
    const int g0  = wrp * 2;      // two groups (batches) per warp
    const int py  = p0 >> 5;
    const int px0 = p0 & 31;

    float* ss = (float*)colbuf;   // flat stage view (group region = 2*REG floats)

    // ---- issue all x loads first (8-deep MLP over block startup) ----
    const int seg = l >> 3;
    const int c4  = (l & 7) * 4;
    float4 xr[8];
#pragma unroll
    for (int i = 0; i < 8; ++i) {
        const int q   = i * 4 + seg;
        const int gof = q >> 4;
        const int r   = q & 15;
        const int b   = bg * 16 + g0 + gof;
        xr[i] = *(const float4*)(x + (size_t)b * (Hdim * Wdim)
                                   + (size_t)(py * 16 + r) * Wdim
                                   + px0 * 16 + c4);
    }

    // ---- stage S transposed while x loads are in flight ----
    {
        const int ky = t >> 4;
        const int kx = t & 15;
#pragma unroll
        for (int hh = 0; hh < 2; ++hh)
            sSt[hh][kx * 20 + ky] = g_S[(p0 + hh) * 256 + t];
    }
    __syncthreads();

    // ---- stage x (coalesced registers -> smem) ----
#pragma unroll
    for (int i = 0; i < 8; ++i) {
        const int q   = i * 4 + seg;
        const int gof = q >> 4;
        const int r   = q & 15;
        *(float4*)(ss + (g0 + gof) * (2 * REG) + r * 36 + c4) = xr[i];
    }
    __syncwarp();

    const int g  = g0 + (l >> 4);  // this lane's group (batch)
    const int ln = l & 15;         // row / task index within group
    float2* buf = colbuf[g];
    float* srow = ss + g * (2 * REG) + ln * 36;

    float zr[16], zi[16];

    // ---- phase 1: read own row pair from stage, packed row FFT ----
#pragma unroll
    for (int qq = 0; qq < 4; ++qq) {
        float4 va = *(const float4*)(srow + qq * 4);
        float4 vb = *(const float4*)(srow + 16 + qq * 4);
        zr[qq*4+0]=va.x; zr[qq*4+1]=va.y; zr[qq*4+2]=va.z; zr[qq*4+3]=va.w;
        zi[qq*4+0]=vb.x; zi[qq*4+1]=vb.y; zi[qq*4+2]=vb.z; zi[qq*4+3]=vb.w;
    }
    fft16<-1>(zr, zi);

    // Hermitian unpack, store strip-major: slot [k*TS + ln]
    buf[0 * TS + ln]       = make_float2(zr[0], zr[8]);   // A: (X[r,0], X[r,8])
    buf[(8 + 0) * TS + ln] = make_float2(zi[0], zi[8]);   // B
#pragma unroll
    for (int k = 1; k <= 7; ++k) {
        const int m = 16 - k;
        buf[k * TS + ln]       = make_float2(0.5f * (zr[k] + zr[m]), 0.5f * (zi[k] - zi[m]));
        buf[(8 + k) * TS + ln] = make_float2(0.5f * (zi[k] + zi[m]), 0.5f * (zr[m] - zr[k]));
    }
    __syncwarp();

    // ---- phase 2: column task s = ln (strip s), vectorized strip read ----
    {
        const int tile = ln >> 3;
        const int tt   = ln & 7;
        const float4* sp4 = (const float4*)(buf + ln * TS);   // 144*ln bytes: 16B aligned
#pragma unroll
        for (int q2 = 0; q2 < 8; ++q2) {
            const float4 v = sp4[q2];
            zr[q2*2+0] = v.x;  zi[q2*2+0] = v.y;
            zr[q2*2+1] = v.z;  zi[q2*2+1] = v.w;
        }

        fft16<-1>(zr, zi);

        const float* Sp = sSt[tile];
        if (tt == 0) {
            // packed real cols 0 & 8: S[ky,0]=Sp[ky], S[ky,8]=Sp[160+ky]
#pragma unroll
            for (int ky = 0; ky <= 8; ++ky) {
                const int m = (16 - ky) & 15;
                const float s0 = Sp[ky];
                const float s8 = Sp[160 + ky];
                const float c0r = 0.5f * (zr[ky] + zr[m]);
                const float c0i = 0.5f * (zi[ky] - zi[m]);
                const float c8r = 0.5f * (zi[ky] + zi[m]);
                const float c8i = 0.5f * (zr[m] - zr[ky]);
                const float ar = c0r * s0, ai = c0i * s0;
                const float br = c8r * s8, bi = c8i * s8;
                zr[ky] = ar - bi;  zi[ky] = ai + br;
                if (m != ky) { zr[m] = ar + bi; zi[m] = br - ai; }
            }
        } else {
            const float4* Sc = (const float4*)(Sp + tt * 20);
#pragma unroll
            for (int q2 = 0; q2 < 4; ++q2) {
                const float4 s4 = Sc[q2];
                zr[q2*4+0] *= s4.x;  zi[q2*4+0] *= s4.x;
                zr[q2*4+1] *= s4.y;  zi[q2*4+1] *= s4.y;
                zr[q2*4+2] *= s4.z;  zi[q2*4+2] *= s4.z;
                zr[q2*4+3] *= s4.w;  zi[q2*4+3] *= s4.w;
            }
        }

        fft16<1>(zr, zi);

        // all lanes must finish READING strips before row-major overwrite
        __syncwarp();
#pragma unroll
        for (int r = 0; r < 16; ++r) buf[r * TS + ln] = make_float2(zr[r], zi[r]);
    }
    __syncwarp();

    // ---- phase 3: vectorized row read, Hermitian-extend, packed inv FFT ----
    {
        float2 wrow[16];
        const float4* rp4 = (const float4*)(buf + ln * TS);
#pragma unroll
        for (int q2 = 0; q2 < 8; ++q2) {
            const float4 v = rp4[q2];
            wrow[q2*2+0] = make_float2(v.x, v.y);
            wrow[q2*2+1] = make_float2(v.z, v.w);
        }
        // slot s (0..7): task s of A (s=0 packed cols 0&8); slot 8+s: B
        zr[0] = wrow[0].x;  zi[0] = wrow[8].x;
        zr[8] = wrow[0].y;  zi[8] = wrow[8].y;
#pragma unroll
        for (int k = 1; k <= 7; ++k) {
            const float2 a = wrow[k];        // W_A[ln,k]
            const float2 c = wrow[8 + k];    // W_B[ln,k]
            zr[k]      = a.x - c.y;   zi[k]      = a.y + c.x;   // W_A + i W_B
            zr[16 - k] = a.x + c.y;   zi[16 - k] = c.x - a.y;   // conj ext
        }
    }
    fft16<1>(zr, zi);

    // ---- epilogue: bias direct from global (L1-hot, contiguous per lane) ----
    {
        const float* bp = bias + p0 * 256 + ln * 16;
#pragma unroll
        for (int j = 0; j < 16; j += 4) {
            const float4 ba = *(const float4*)(bp + j);
            const float4 bb = *(const float4*)(bp + 256 + j);
            float4 oa, ob;
            oa.x = zr[j+0] + ba.x;  oa.y = zr[j+1] + ba.y;
            oa.z = zr[j+2] + ba.z;  oa.w = zr[j+3] + ba.w;
            ob.x = zi[j+0] + bb.x;  ob.y = zi[j+1] + bb.y;
            ob.z = zi[j+2] + bb.z;  ob.w = zi[j+3] + bb.w;
            *(float4*)(srow + j)      = oa;
            *(float4*)(srow + 16 + j) = ob;
        }
    }
    __syncwarp();

    // ---- staged coalesced store: 8 x STG.128, full sectors ----
#pragma unroll
    for (int i = 0; i < 8; ++i) {
        const int q   = i * 4 + seg;
        const int gof = q >> 4;
        const int r   = q & 15;
        const int gg  = g0 + gof;
        const int b   = bg * 16 + gg;
        float4 v = *(const float4*)(ss + gg * (2 * REG) + r * 36 + c4);
        *(float4*)(y + (size_t)b * (Hdim * Wdim)
                     + (size_t)(py * 16 + r) * Wdim
                     + px0 * 16 + c4) = v;
    }
}

extern "C" void kernel_launch(void* const* d_in, const int* in_sizes, int n_in,
                              void* d_out, int out_size)
{
    const float* x      = (const float*)d_in[0];
    const float* logits = (const float*)d_in[1];
    const float* mu     = (const float*)d_in[2];
    const float* sigma  = (const float*)d_in[3];
    const float* bias   = (const float*)d_in[4];
    float* y = (float*)d_out;

    make_S_kernel<<<Pn, 256>>>(logits, mu, sigma);
    patch_spectral_kernel<<<2048, 256>>>(x, bias, y);
}

// round 9
// speedup vs baseline: 3.5974x; 3.5974x over previous
#include <cuda_runtime.h>
#include <cuda_bf16.h>

#define Hdim 512
#define Wdim 512
#define Qn 3
#define Pn 1024
#define Bn 64
#define JITTER 1e-6f

#define TS 18      // strip/row stride in float2 (16B-aligned strip bases)
#define REG 296    // float2 per group region

typedef unsigned long long u64;

// ---- f32x2 packed helpers: u64 = (float lo = re, float hi = im) ----
__device__ __forceinline__ u64 pk2(float lo, float hi) {
    u64 d; asm("mov.b64 %0, {%1, %2};" : "=l"(d) : "f"(lo), "f"(hi)); return d;
}
__device__ __forceinline__ void upk2(u64 v, float& lo, float& hi) {
    asm("mov.b64 {%0, %1}, %2;" : "=f"(lo), "=f"(hi) : "l"(v));
}
__device__ __forceinline__ u64 add2(u64 a, u64 b) {
    u64 d; asm("add.rn.f32x2 %0, %1, %2;" : "=l"(d) : "l"(a), "l"(b)); return d;
}
__device__ __forceinline__ u64 mul2(u64 a, u64 b) {
    u64 d; asm("mul.rn.f32x2 %0, %1, %2;" : "=l"(d) : "l"(a), "l"(b)); return d;
}
__device__ __forceinline__ u64 fma2(u64 a, u64 b, u64 c) {
    u64 d; asm("fma.rn.f32x2 %0, %1, %2, %3;" : "=l"(d) : "l"(a), "l"(b), "l"(c)); return d;
}
// a - b  (via fma with (-1,-1) so we don't depend on sub.rn.f32x2 existing)
__device__ __forceinline__ u64 sub2(u64 a, u64 b) {
    return fma2(b, pk2(-1.0f, -1.0f), a);
}
__device__ __forceinline__ u64 swp2(u64 v) {
    float a, b; upk2(v, a, b); return pk2(b, a);
}

// Precomputed symmetrized spectrum: S_sym[p][ky*16+kx] / 256
__device__ float g_S[Pn * 256];

// ---------------------------------------------------------------------------
// Kernel A: build S per patch (separable Gaussians), index-symmetrized.
// ---------------------------------------------------------------------------
__global__ __launch_bounds__(256) void make_S_kernel(
    const float* __restrict__ logits,
    const float* __restrict__ mu,
    const float* __restrict__ sigma)
{
    __shared__ float w[4];
    __shared__ float gy[6][16];
    __shared__ float gx[6][16];
    __shared__ float sAcc[256];

    const int p = blockIdx.x;
    const int t = threadIdx.x;

    if (t == 0) {
        const float l0 = logits[p * Qn + 0];
        const float l1 = logits[p * Qn + 1];
        const float l2 = logits[p * Qn + 2];
        const float mx = fmaxf(l0, fmaxf(l1, l2));
        const float e0 = expf(l0 - mx);
        const float e1 = expf(l1 - mx);
        const float e2 = expf(l2 - mx);
        const float inv = 1.0f / (e0 + e1 + e2);
        w[0] = e0 * inv; w[1] = e1 * inv; w[2] = e2 * inv;
    }
    if (t < 192) {
        const int axis = t / 96;
        const int rem  = t % 96;
        const int qs   = rem >> 4;
        const int k    = rem & 15;
        const int q    = qs >> 1;
        const int sgn  = qs & 1;
        const float f  = (float)(k < 8 ? k : k - 16) * (1.0f / 16.0f);
        const int base = (p * Qn + q) * 2;
        const float m  = mu[base + axis];
        const float s  = sigma[base + axis];
        const float d  = (sgn ? (f + m) : (f - m)) / s;
        const float v  = expf(-0.5f * d * d);
        if (axis == 0) gy[qs][k] = v; else gx[qs][k] = v;
    }
    __syncthreads();

    const int ky = t >> 4;
    const int kx = t & 15;
    float acc = 0.0f;
#pragma unroll
    for (int q = 0; q < Qn; ++q) {
        acc += w[q] * (gy[2 * q][ky] * gx[2 * q][kx] +
                       gy[2 * q + 1][ky] * gx[2 * q + 1][kx]);
    }
    sAcc[t] = acc;
    __syncthreads();

    const int tm = (((16 - ky) & 15) << 4) | ((16 - kx) & 15);
    const float ssym = 0.5f * (sAcc[t] + sAcc[tm]) + JITTER;
    g_S[p * 256 + t] = ssym * (1.0f / 256.0f);
}

// ---------------------------------------------------------------------------
// Packed 16-point complex FFT on AoS f32x2 values. DIR=-1 fwd, +1 inv.
// Twiddle w_j = CT[j] + i*DIR*ST[j]; w_{j+4} = i*w_j.
// ---------------------------------------------------------------------------
template<int DIR>
__device__ __forceinline__ void fft16p(u64 z[16]) {
#define SWAPZ(a,b) { u64 _t = z[a]; z[a] = z[b]; z[b] = _t; }
    SWAPZ(1, 8) SWAPZ(2, 4) SWAPZ(3, 12) SWAPZ(5, 10) SWAPZ(7, 14) SWAPZ(11, 13)
#undef SWAPZ

    // t = w * z[B] with w = (C, SN);  z[B] = z[A]-t; z[A] = z[A]+t
#define BFLY(A, B, C, SN) { \
    u64 _t = fma2(swp2(z[B]), pk2(-(SN), (SN)), mul2(z[B], pk2((C), (C)))); \
    z[B] = sub2(z[A], _t);  z[A] = add2(z[A], _t); }

#define BFLY1(A, B) { \
    u64 _t = z[B];  z[B] = sub2(z[A], _t);  z[A] = add2(z[A], _t); }

    // w = i*DIR : DIR=-1 -> t=(im,-re)=swp*(1,-1) ; DIR=+1 -> t=(-im,re)=swp*(-1,1)
#define BFLYI(A, B) { \
    u64 _t = mul2(swp2(z[B]), (DIR < 0) ? pk2(1.0f, -1.0f) : pk2(-1.0f, 1.0f)); \
    z[B] = sub2(z[A], _t);  z[A] = add2(z[A], _t); }

    const float R2  = 0.7071067811865476f;
    const float CT1 = 0.9238795325112867f;
    const float ST1 = 0.3826834323650898f;

    // stage 1 (len 2): all w=1
    BFLY1(0,1)  BFLY1(2,3)  BFLY1(4,5)  BFLY1(6,7)
    BFLY1(8,9)  BFLY1(10,11) BFLY1(12,13) BFLY1(14,15)

    // stage 2 (len 4)
    BFLY1(0,2)  BFLYI(1,3)
    BFLY1(4,6)  BFLYI(5,7)
    BFLY1(8,10) BFLYI(9,11)
    BFLY1(12,14) BFLYI(13,15)

    // stage 3 (len 8)
    BFLY1(0,4)  BFLY(1,5,  R2, (float)DIR * R2)  BFLYI(2,6)  BFLY(3,7,  -R2, (float)DIR * R2)
    BFLY1(8,12) BFLY(9,13, R2, (float)DIR * R2)  BFLYI(10,14) BFLY(11,15, -R2, (float)DIR * R2)

    // stage 4 (len 16)
    BFLY1(0,8)
    BFLY(1,9,   CT1, (float)DIR * ST1)
    BFLY(2,10,  R2,  (float)DIR * R2)
    BFLY(3,11,  ST1, (float)DIR * CT1)
    BFLYI(4,12)
    BFLY(5,13, -ST1, (float)DIR * CT1)
    BFLY(6,14, -R2,  (float)DIR * R2)
    BFLY(7,15, -CT1, (float)DIR * ST1)

#undef BFLY
#undef BFLY1
#undef BFLYI
}

// ---------------------------------------------------------------------------
// Kernel B: block = one adjacent patch pair (A,B) x 16 batches.
// Round 9: all FFT/complex math in packed f32x2 (AoS complex in u64 regs).
// Data movement identical to round 8.
// ---------------------------------------------------------------------------
__global__ __launch_bounds__(256, 4) void patch_spectral_kernel(
    const float* __restrict__ x,
    const float* __restrict__ bias,
    float* __restrict__ y)
{
    __shared__ __align__(16) float2 colbuf[16][REG];
    __shared__ float sSt[2][336];        // transposed S: sSt[h][kx*20+ky]

    const int pp = blockIdx.x & 511;
    const int bg = blockIdx.x >> 9;
    const int t  = threadIdx.x;
    const int p0 = pp * 2;

    const int wrp = t >> 5;
    const int l   = t & 31;
    const int g0  = wrp * 2;
    const int py  = p0 >> 5;
    const int px0 = p0 & 31;

    float* ss = (float*)colbuf;

    // ---- issue all x loads first (8-deep MLP over block startup) ----
    const int seg = l >> 3;
    const int c4  = (l & 7) * 4;
    float4 xrg[8];
#pragma unroll
    for (int i = 0; i < 8; ++i) {
        const int q   = i * 4 + seg;
        const int gof = q >> 4;
        const int r   = q & 15;
        const int b   = bg * 16 + g0 + gof;
        xrg[i] = *(const float4*)(x + (size_t)b * (Hdim * Wdim)
                                    + (size_t)(py * 16 + r) * Wdim
                                    + px0 * 16 + c4);
    }

    // ---- stage S transposed while x loads are in flight ----
    {
        const int ky = t >> 4;
        const int kx = t & 15;
#pragma unroll
        for (int hh = 0; hh < 2; ++hh)
            sSt[hh][kx * 20 + ky] = g_S[(p0 + hh) * 256 + t];
    }
    __syncthreads();

    // ---- stage x (coalesced registers -> smem) ----
#pragma unroll
    for (int i = 0; i < 8; ++i) {
        const int q   = i * 4 + seg;
        const int gof = q >> 4;
        const int r   = q & 15;
        *(float4*)(ss + (g0 + gof) * (2 * REG) + r * 36 + c4) = xrg[i];
    }
    __syncwarp();

    const int g  = g0 + (l >> 4);
    const int ln = l & 15;
    float2* buf = colbuf[g];
    float* srow = ss + g * (2 * REG) + ln * 36;

    u64 z[16];

    // ---- phase 1: pack rows A,B as complex AoS, packed row FFT ----
#pragma unroll
    for (int qq = 0; qq < 4; ++qq) {
        float4 va = *(const float4*)(srow + qq * 4);
        float4 vb = *(const float4*)(srow + 16 + qq * 4);
        z[qq*4+0] = pk2(va.x, vb.x);
        z[qq*4+1] = pk2(va.y, vb.y);
        z[qq*4+2] = pk2(va.z, vb.z);
        z[qq*4+3] = pk2(va.w, vb.w);
    }
    fft16p<-1>(z);

    // Hermitian unpack, store strip-major
    {
        float r0, i0, r8, i8;
        upk2(z[0], r0, i0);
        upk2(z[8], r8, i8);
        buf[0 * TS + ln]       = make_float2(r0, r8);   // A: (X[r,0], X[r,8])
        buf[(8 + 0) * TS + ln] = make_float2(i0, i8);   // B
    }
#pragma unroll
    for (int k = 1; k <= 7; ++k) {
        const int m = 16 - k;
        const u64 conjm = mul2(z[m], pk2(1.0f, -1.0f));
        const u64 XA = mul2(add2(z[k], conjm), pk2(0.5f, 0.5f));
        const u64 d  = sub2(z[k], conjm);
        const u64 XB = mul2(swp2(d), pk2(0.5f, -0.5f));
        *reinterpret_cast<u64*>(buf + k * TS + ln)       = XA;
        *reinterpret_cast<u64*>(buf + (8 + k) * TS + ln) = XB;
    }
    __syncwarp();

    // ---- phase 2: column task (tile = ln>>3, tt = ln&7) ----
    {
        const int tile = ln >> 3;
        const int tt   = ln & 7;
        const ulonglong2* sp2 = (const ulonglong2*)(buf + ln * TS);
#pragma unroll
        for (int q2 = 0; q2 < 8; ++q2) {
            const ulonglong2 v = sp2[q2];
            z[q2*2+0] = v.x;
            z[q2*2+1] = v.y;
        }

        fft16p<-1>(z);

        const float* Sp = sSt[tile];
        if (tt == 0) {
            // packed real cols 0 & 8: S[ky,0]=Sp[ky], S[ky,8]=Sp[160+ky]
#pragma unroll
            for (int ky = 0; ky <= 8; ++ky) {
                const int m = (16 - ky) & 15;
                const u64 conjv = mul2(z[m], pk2(1.0f, -1.0f));
                const u64 C0 = mul2(add2(z[ky], conjv), pk2(0.5f, 0.5f));
                const u64 w1 = sub2(z[ky], conjv);
                const u64 C8 = mul2(swp2(w1), pk2(0.5f, -0.5f));
                const float s0 = Sp[ky];
                const float s8 = Sp[160 + ky];
                const u64 A  = mul2(C0, pk2(s0, s0));
                const u64 B8 = mul2(C8, pk2(s8, s8));
                const u64 iB = mul2(swp2(B8), pk2(-1.0f, 1.0f));   // i*B8
                z[ky] = add2(A, iB);
                if (m != ky)
                    z[m] = mul2(sub2(A, iB), pk2(1.0f, -1.0f));    // conj(A - i*B8)
            }
        } else {
            const float4* Sc = (const float4*)(Sp + tt * 20);
#pragma unroll
            for (int q2 = 0; q2 < 4; ++q2) {
                const float4 s4 = Sc[q2];
                z[q2*4+0] = mul2(z[q2*4+0], pk2(s4.x, s4.x));
                z[q2*4+1] = mul2(z[q2*4+1], pk2(s4.y, s4.y));
                z[q2*4+2] = mul2(z[q2*4+2], pk2(s4.z, s4.z));
                z[q2*4+3] = mul2(z[q2*4+3], pk2(s4.w, s4.w));
            }
        }

        fft16p<1>(z);

        __syncwarp();   // all lanes done READING strips before overwrite
#pragma unroll
        for (int r = 0; r < 16; ++r)
            *reinterpret_cast<u64*>(buf + r * TS + ln) = z[r];
    }
    __syncwarp();

    // ---- phase 3: Hermitian-extend W rows (packed), inverse row FFT ----
    {
        u64 wrow[16];
        const ulonglong2* rp2 = (const ulonglong2*)(buf + ln * TS);
#pragma unroll
        for (int q2 = 0; q2 < 8; ++q2) {
            const ulonglong2 v = rp2[q2];
            wrow[q2*2+0] = v.x;
            wrow[q2*2+1] = v.y;
        }
        {
            float a0x, a0y, b0x, b0y;
            upk2(wrow[0], a0x, a0y);
            upk2(wrow[8], b0x, b0y);
            z[0] = pk2(a0x, b0x);
            z[8] = pk2(a0y, b0y);
        }
#pragma unroll
        for (int k = 1; k <= 7; ++k) {
            const u64 Wa = wrow[k];
            const u64 Wb = wrow[8 + k];
            const u64 iWb = mul2(swp2(Wb), pk2(-1.0f, 1.0f));      // i*W_B
            z[k]      = add2(Wa, iWb);                              // W_A + i W_B
            z[16 - k] = mul2(sub2(Wa, iWb), pk2(1.0f, -1.0f));      // conj(W_A - i W_B)
        }
    }
    fft16p<1>(z);

    // ---- epilogue: unpack, +bias (direct global), store into stage ----
    {
        float yA[16], yB[16];
#pragma unroll
        for (int j = 0; j < 16; ++j) upk2(z[j], yA[j], yB[j]);

        const float* bp = bias + p0 * 256 + ln * 16;
#pragma unroll
        for (int j = 0; j < 16; j += 4) {
            const float4 ba = *(const float4*)(bp + j);
            const float4 bb = *(const float4*)(bp + 256 + j);
            float4 oa, ob;
            oa.x = yA[j+0] + ba.x;  oa.y = yA[j+1] + ba.y;
            oa.z = yA[j+2] + ba.z;  oa.w = yA[j+3] + ba.w;
            ob.x = yB[j+0] + bb.x;  ob.y = yB[j+1] + bb.y;
            ob.z = yB[j+2] + bb.z;  ob.w = yB[j+3] + bb.w;
            *(float4*)(srow + j)      = oa;
            *(float4*)(srow + 16 + j) = ob;
        }
    }
    __syncwarp();

    // ---- staged coalesced store: 8 x STG.128, full sectors ----
#pragma unroll
    for (int i = 0; i < 8; ++i) {
        const int q   = i * 4 + seg;
        const int gof = q >> 4;
        const int r   = q & 15;
        const int gg  = g0 + gof;
        const int b   = bg * 16 + gg;
        float4 v = *(const float4*)(ss + gg * (2 * REG) + r * 36 + c4);
        *(float4*)(y + (size_t)b * (Hdim * Wdim)
                     + (size_t)(py * 16 + r) * Wdim
                     + px0 * 16 + c4) = v;
    }
}

extern "C" void kernel_launch(void* const* d_in, const int* in_sizes, int n_in,
                              void* d_out, int out_size)
{
    const float* x      = (const float*)d_in[0];
    const float* logits = (const float*)d_in[1];
    const float* mu     = (const float*)d_in[2];
    const float* sigma  = (const float*)d_in[3];
    const float* bias   = (const float*)d_in[4];
    float* y = (float*)d_out;

    make_S_kernel<<<Pn, 256>>>(logits, mu, sigma);
    patch_spectral_kernel<<<2048, 256>>>(x, bias, y);
}